// round 11
// baseline (speedup 1.0000x reference)
#include <cuda_runtime.h>
#include <math.h>

#define NN    1024      // nodes / seq len
#define NE    16384     // edges
#define BSZ   16
#define LEN0  8500
#define HH    640
#define G4    2560      // 4*H
#define TT    1024
#define SB    128       // scan blocks (<= #SMs for co-residency)

// ---------------- device scratch (no allocations allowed) ----------------
__device__ float g_xw[TT * G4];        // 10.5 MB input projection
__device__ float g_seqA[TT * HH];
__device__ float g_seqB[TT * HH];
__device__ __align__(16) float g_hbuf[2 * HH];   // double-buffered h
__device__ int   g_flags[SB];          // per-CTA epoch flags (no atomics)
__device__ float g_gh[NN * 320];       // gcn xW
__device__ float g_agg[NN * 320];      // gcn aggregation
__device__ float g_deg[NN];
__device__ float g_dinv[NN];
__device__ float g_cs1[320];           // column sums
__device__ float g_cs2[320];           // column sums of squares

// ---------------- utility ----------------
__global__ void k_zero_f(float* p, int n) {
    int st = gridDim.x * blockDim.x;
    for (int i = blockIdx.x * blockDim.x + threadIdx.x; i < n; i += st) p[i] = 0.f;
}
__global__ void k_zero_flags() {
    int i = threadIdx.x;
    if (i < SB) g_flags[i] = 0;
}

// ---------------- SGEMM  C[M,N] = A[M,K] * B[N,K]^T + b0[n] + b1[n] ----------------
// BM=128, BN=128, BK=8, 256 threads, 8x8 microtile, float4 everywhere.
// Requires M%128==0, N%128==0, K%4==0 (rows 16B aligned). K tail (K%8) guarded.
__global__ void __launch_bounds__(256, 2) k_gemm_nt(
    const float* __restrict__ A, const float* __restrict__ B,
    const float* __restrict__ b0, const float* __restrict__ b1,
    float* __restrict__ C, int M, int N, int K)
{
    __shared__ __align__(16) float As[8][132];
    __shared__ __align__(16) float Bs[8][132];
    const int tid = threadIdx.x;
    const int bm = blockIdx.y * 128;
    const int bn = blockIdx.x * 128;
    const int ty = tid >> 4, tx = tid & 15;     // 16x16 thread grid
    const int row = tid >> 1;                    // 0..127 loader row
    const int kq  = (tid & 1) * 4;               // 0 or 4
    const float* Ap = A + (size_t)(bm + row) * K;
    const float* Bp = B + (size_t)(bn + row) * K;

    float acc[8][8];
    #pragma unroll
    for (int i = 0; i < 8; i++)
        #pragma unroll
        for (int j = 0; j < 8; j++) acc[i][j] = 0.f;

    for (int k0 = 0; k0 < K; k0 += 8) {
        float4 av = make_float4(0.f, 0.f, 0.f, 0.f);
        float4 bv = make_float4(0.f, 0.f, 0.f, 0.f);
        if (k0 + kq < K) {                        // K%4==0 -> whole float4 in-range
            av = *(const float4*)&Ap[k0 + kq];
            bv = *(const float4*)&Bp[k0 + kq];
        }
        As[kq + 0][row] = av.x; As[kq + 1][row] = av.y;
        As[kq + 2][row] = av.z; As[kq + 3][row] = av.w;
        Bs[kq + 0][row] = bv.x; Bs[kq + 1][row] = bv.y;
        Bs[kq + 2][row] = bv.z; Bs[kq + 3][row] = bv.w;
        __syncthreads();
        #pragma unroll
        for (int kk = 0; kk < 8; kk++) {
            float4 a0 = *(const float4*)&As[kk][ty * 8];
            float4 a1 = *(const float4*)&As[kk][ty * 8 + 4];
            float4 r0 = *(const float4*)&Bs[kk][tx * 8];
            float4 r1 = *(const float4*)&Bs[kk][tx * 8 + 4];
            float ra[8] = {a0.x, a0.y, a0.z, a0.w, a1.x, a1.y, a1.z, a1.w};
            float rb[8] = {r0.x, r0.y, r0.z, r0.w, r1.x, r1.y, r1.z, r1.w};
            #pragma unroll
            for (int i = 0; i < 8; i++)
                #pragma unroll
                for (int j = 0; j < 8; j++)
                    acc[i][j] += ra[i] * rb[j];
        }
        __syncthreads();
    }
    #pragma unroll
    for (int i = 0; i < 8; i++) {
        int m = bm + ty * 8 + i;
        int n0 = bn + tx * 8;
        #pragma unroll
        for (int j = 0; j < 8; j++) {
            int n = n0 + j;
            C[(size_t)m * N + n] = acc[i][j] + b0[n] + b1[n];
        }
    }
}

// ---------------- GEMM NN for GCN:  C[1024,N] = A[1024,K] * B[K,N] ----------------
__global__ void __launch_bounds__(256) k_gemm_nn(
    const float* __restrict__ A, const float* __restrict__ B,
    float* __restrict__ C, int N, int K)
{
    __shared__ float As[8][64];
    __shared__ float Bs[8][64];
    const int tid = threadIdx.x;
    const int bm = blockIdx.y * 64;
    const int bn = blockIdx.x * 64;
    const int ty = tid >> 4, tx = tid & 15;
    const int arow = tid >> 2, ak = (tid & 3) * 2;
    const int bkr = tid >> 5, bc = (tid & 31) * 2;
    float acc[4][4] = {};
    for (int k0 = 0; k0 < K; k0 += 8) {
        #pragma unroll
        for (int i = 0; i < 2; i++) {
            int kk = k0 + ak + i;
            As[ak + i][arow] = (kk < K) ? A[(bm + arow) * K + kk] : 0.f;
        }
        #pragma unroll
        for (int i = 0; i < 2; i++) {
            int n = bn + bc + i;
            Bs[bkr][bc + i] = (k0 + bkr < K && n < N) ? B[(k0 + bkr) * N + n] : 0.f;
        }
        __syncthreads();
        #pragma unroll
        for (int kk = 0; kk < 8; kk++) {
            float ra[4], rb[4];
            #pragma unroll
            for (int i = 0; i < 4; i++) ra[i] = As[kk][ty * 4 + i];
            #pragma unroll
            for (int j = 0; j < 4; j++) rb[j] = Bs[kk][tx * 4 + j];
            #pragma unroll
            for (int i = 0; i < 4; i++)
                #pragma unroll
                for (int j = 0; j < 4; j++)
                    acc[i][j] += ra[i] * rb[j];
        }
        __syncthreads();
    }
    #pragma unroll
    for (int i = 0; i < 4; i++) {
        int m = bm + ty * 4 + i;
        #pragma unroll
        for (int j = 0; j < 4; j++) {
            int n = bn + tx * 4 + j;
            if (n < N) C[m * N + n] = acc[i][j];
        }
    }
}

// ---------------- LSTM recurrent scan ----------------
// 128 blocks x 160 threads. Warp w of block b owns element j = 5b+w and keeps
// all four Whh gate rows in registers (20 float4 per thread).
// Grid barrier: atomic-free all-to-all flags. Each CTA stores epoch t+1 to its
// own flag word (threadfence before -> release-cumulative); warp 0 polls all
// 128 flags (4 per lane + __all_sync). No contended atomic line.
__global__ void __launch_bounds__(160) k_lstm_scan(
    const float* __restrict__ xw,    // [T, 4H]
    const float* __restrict__ Whh,   // [4H, H]
    float* __restrict__ out)         // [T, H]
{
    __shared__ __align__(16) float h_s[HH];
    const int tid  = threadIdx.x;
    const int wid  = tid >> 5;
    const int lane = tid & 31;
    const int j    = blockIdx.x * 5 + wid;

    // weight layout: w?[k4] covers h indices [4*lane + 128*k4, +4)
    float4 wI[5], wF[5], wG[5], wO[5];
    #pragma unroll
    for (int k4 = 0; k4 < 5; k4++) {
        int off = 4 * lane + 128 * k4;
        wI[k4] = *(const float4*)&Whh[(size_t)(0 * HH + j) * HH + off];
        wF[k4] = *(const float4*)&Whh[(size_t)(1 * HH + j) * HH + off];
        wG[k4] = *(const float4*)&Whh[(size_t)(2 * HH + j) * HH + off];
        wO[k4] = *(const float4*)&Whh[(size_t)(3 * HH + j) * HH + off];
    }
    #pragma unroll
    for (int i = 0; i < 4; i++) h_s[tid + 160 * i] = 0.f;
    float c = 0.f;                 // live in lane 0 of each warp
    float xwv = (lane < 4) ? __ldg(&xw[lane * HH + j]) : 0.f;
    __syncthreads();

    for (int t = 0; t < TT; t++) {
        float aI = 0.f, aF = 0.f, aG = 0.f, aO = 0.f;
        #pragma unroll
        for (int k4 = 0; k4 < 5; k4++) {
            float4 hv = *(const float4*)&h_s[4 * lane + 128 * k4];
            aI += wI[k4].x * hv.x + wI[k4].y * hv.y + wI[k4].z * hv.z + wI[k4].w * hv.w;
            aF += wF[k4].x * hv.x + wF[k4].y * hv.y + wF[k4].z * hv.z + wF[k4].w * hv.w;
            aG += wG[k4].x * hv.x + wG[k4].y * hv.y + wG[k4].z * hv.z + wG[k4].w * hv.w;
            aO += wO[k4].x * hv.x + wO[k4].y * hv.y + wO[k4].z * hv.z + wO[k4].w * hv.w;
        }
        #pragma unroll
        for (int off = 16; off; off >>= 1) {
            aI += __shfl_down_sync(0xffffffffu, aI, off);
            aF += __shfl_down_sync(0xffffffffu, aF, off);
            aG += __shfl_down_sync(0xffffffffu, aG, off);
            aO += __shfl_down_sync(0xffffffffu, aO, off);
        }
        float xI = __shfl_sync(0xffffffffu, xwv, 0);
        float xF = __shfl_sync(0xffffffffu, xwv, 1);
        float xG = __shfl_sync(0xffffffffu, xwv, 2);
        float xO = __shfl_sync(0xffffffffu, xwv, 3);

        const int nb = (t + 1) & 1;
        if (lane == 0) {
            float iv = __fdividef(1.f, 1.f + __expf(-(aI + xI)));
            float fv = __fdividef(1.f, 1.f + __expf(-(aF + xF)));
            float gv = 1.f - __fdividef(2.f, 1.f + __expf(2.f * (aG + xG)));
            float ov = __fdividef(1.f, 1.f + __expf(-(aO + xO)));
            c = fv * c + iv * gv;
            float hv = ov * (1.f - __fdividef(2.f, 1.f + __expf(2.f * c)));
            out[t * HH + j] = hv;
            g_hbuf[nb * HH + j] = hv;
        }
        // prefetch next step's xw while the barrier drains
        float xnext = 0.f;
        if (lane < 4 && t + 1 < TT) xnext = __ldg(&xw[(size_t)(t + 1) * G4 + lane * HH + j]);

        __syncthreads();                   // this CTA's h writes done
        if (wid == 0) {
            __threadfence();               // publish h (release-cumulative)
            if (lane == 0) *((volatile int*)&g_flags[blockIdx.x]) = t + 1;
            const int tgt = t + 1;
            const int fi = lane * 4;
            bool done;
            do {
                int f0 = *((volatile int*)&g_flags[fi + 0]);
                int f1 = *((volatile int*)&g_flags[fi + 1]);
                int f2 = *((volatile int*)&g_flags[fi + 2]);
                int f3 = *((volatile int*)&g_flags[fi + 3]);
                int mn = min(min(f0, f1), min(f2, f3));
                done = __all_sync(0xffffffffu, mn >= tgt);
            } while (!done);
            __threadfence();               // acquire
        }
        __syncthreads();                   // all CTAs published h(t+1)
        ((float4*)h_s)[tid] = ((const float4*)&g_hbuf[nb * HH])[tid];
        __syncthreads();                   // h_s ready for next step
        xwv = xnext;
    }
}

// ---------------- GCN helpers ----------------
__global__ void k_deg_count(const int* __restrict__ ei) {
    int e = blockIdx.x * blockDim.x + threadIdx.x;
    if (e < NE) atomicAdd(&g_deg[ei[NE + e]], 1.f);
}
__global__ void k_deg_fin() {
    int i = blockIdx.x * blockDim.x + threadIdx.x;
    if (i < NN) g_dinv[i] = rsqrtf(g_deg[i] + 1.f);   // +1 self loop
}
__global__ void k_scatter(const int* __restrict__ ei, const float* __restrict__ h, int N) {
    int total = (NE + NN) * N;
    int st = gridDim.x * blockDim.x;
    for (int idx = blockIdx.x * blockDim.x + threadIdx.x; idx < total; idx += st) {
        int e = idx / N, cidx = idx - e * N;
        int s, d;
        if (e < NE) { s = ei[e]; d = ei[NE + e]; }
        else        { s = e - NE; d = s; }
        atomicAdd(&g_agg[d * N + cidx], g_dinv[s] * g_dinv[d] * h[s * N + cidx]);
    }
}
__global__ void k_act_stats(const float* __restrict__ b, int N) {
    int total = NN * N;
    int st = gridDim.x * blockDim.x;
    for (int idx = blockIdx.x * blockDim.x + threadIdx.x; idx < total; idx += st) {
        int cidx = idx % N;
        float v = g_agg[idx] + b[cidx];
        v = (v > 0.f) ? v : 0.01f * v;     // leaky_relu slope 0.01
        g_agg[idx] = v;
        atomicAdd(&g_cs1[cidx], v);
        atomicAdd(&g_cs2[cidx], v * v);
    }
}
__global__ void k_bn(float* __restrict__ xout, int N) {
    const float inv = 1.f / (float)NN;
    int total = NN * N;
    int st = gridDim.x * blockDim.x;
    for (int idx = blockIdx.x * blockDim.x + threadIdx.x; idx < total; idx += st) {
        int cidx = idx % N;
        float m  = g_cs1[cidx] * inv;
        float vr = g_cs2[cidx] * inv - m * m;       // biased variance
        xout[idx] = (g_agg[idx] - m) * rsqrtf(vr + 1e-5f);
    }
}

// ---------------- segment-sum pool + FC head (single block) ----------------
__global__ void __launch_bounds__(256) k_pool_fc(
    const float* __restrict__ x,            // [1024, 50]
    const float* __restrict__ gender, const float* __restrict__ handed,
    const float* __restrict__ W1, const float* __restrict__ b1,   // [32,52],[32]
    const float* __restrict__ W2, const float* __restrict__ b2,   // [16,32],[16]
    const float* __restrict__ W3, const float* __restrict__ b3,   // [1,16],[1]
    float* __restrict__ outp)
{
    __shared__ float xp[16][52];
    __shared__ float y1[16][32];
    __shared__ float y2[16][16];
    int tid = threadIdx.x;
    for (int idx = tid; idx < 16 * 50; idx += 256) {
        int bb = idx / 50, cc = idx % 50;
        float s = 0.f;
        for (int r = 0; r < 64; r++) s += x[(bb * 64 + r) * 50 + cc];
        xp[bb][cc] = s;
    }
    if (tid < 16) { xp[tid][50] = gender[tid]; xp[tid][51] = handed[tid]; }
    __syncthreads();
    for (int idx = tid; idx < 16 * 32; idx += 256) {
        int bb = idx >> 5, o = idx & 31;
        float s = b1[o];
        for (int k = 0; k < 52; k++) s += xp[bb][k] * W1[o * 52 + k];
        y1[bb][o] = s;
    }
    __syncthreads();
    {
        int bb = tid >> 4, o = tid & 15;
        float s = b2[o];
        for (int k = 0; k < 32; k++) s += y1[bb][k] * W2[o * 32 + k];
        y2[bb][o] = s;
    }
    __syncthreads();
    if (tid < 16) {
        float s = b3[0];
        for (int k = 0; k < 16; k++) s += y2[tid][k] * W3[k];
        outp[tid] = s;
    }
}

// ---------------- orchestration ----------------
extern "C" void kernel_launch(void* const* d_in, const int* in_sizes, int n_in,
                              void* d_out, int out_size)
{
    const float* x_in   = (const float*)d_in[0];
    const int*   ei     = (const int*)  d_in[1];
    const float* gender = (const float*)d_in[2];
    const float* handed = (const float*)d_in[3];
    const float* Wih[3] = {(const float*)d_in[4],  (const float*)d_in[8],  (const float*)d_in[12]};
    const float* Whh[3] = {(const float*)d_in[5],  (const float*)d_in[9],  (const float*)d_in[13]};
    const float* bih[3] = {(const float*)d_in[6],  (const float*)d_in[10], (const float*)d_in[14]};
    const float* bhh[3] = {(const float*)d_in[7],  (const float*)d_in[11], (const float*)d_in[15]};
    const float* gW[4]  = {(const float*)d_in[16], (const float*)d_in[18], (const float*)d_in[20], (const float*)d_in[22]};
    const float* gB[4]  = {(const float*)d_in[17], (const float*)d_in[19], (const float*)d_in[21], (const float*)d_in[23]};

    float *xw, *seqA, *seqB, *gh, *agg, *deg, *cs1, *cs2;
    cudaGetSymbolAddress((void**)&xw,   g_xw);
    cudaGetSymbolAddress((void**)&seqA, g_seqA);
    cudaGetSymbolAddress((void**)&seqB, g_seqB);
    cudaGetSymbolAddress((void**)&gh,   g_gh);
    cudaGetSymbolAddress((void**)&agg,  g_agg);
    cudaGetSymbolAddress((void**)&deg,  g_deg);
    cudaGetSymbolAddress((void**)&cs1,  g_cs1);
    cudaGetSymbolAddress((void**)&cs2,  g_cs2);
    (void)in_sizes; (void)n_in; (void)out_size;

    dim3 gemmGrid(G4 / 128, TT / 128);   // (20, 8) = 160 CTAs

    // ---- LSTM layer 0 ----
    k_gemm_nt<<<gemmGrid, 256>>>(x_in, Wih[0], bih[0], bhh[0], xw, TT, G4, LEN0);
    k_zero_flags<<<1, SB>>>();
    k_lstm_scan<<<SB, 160>>>(xw, Whh[0], seqA);
    // ---- LSTM layer 1 ----
    k_gemm_nt<<<gemmGrid, 256>>>(seqA, Wih[1], bih[1], bhh[1], xw, TT, G4, HH);
    k_zero_flags<<<1, SB>>>();
    k_lstm_scan<<<SB, 160>>>(xw, Whh[1], seqB);
    // ---- LSTM layer 2 ----
    k_gemm_nt<<<gemmGrid, 256>>>(seqB, Wih[2], bih[2], bhh[2], xw, TT, G4, HH);
    k_zero_flags<<<1, SB>>>();
    k_lstm_scan<<<SB, 160>>>(xw, Whh[2], seqA);

    // ---- degrees / symmetric norm ----
    k_zero_f<<<4, 256>>>(deg, NN);
    k_deg_count<<<64, 256>>>(ei);
    k_deg_fin<<<4, 256>>>();

    // ---- 4 GCN layers ----
    int dims[5] = {HH, 320, 180, 90, 50};
    const float* xcur = seqA;
    float* bufs[2] = {seqB, seqA};
    for (int l = 0; l < 4; l++) {
        int In = dims[l], Out = dims[l + 1];
        k_gemm_nn<<<dim3((Out + 63) / 64, NN / 64), 256>>>(xcur, gW[l], gh, Out, In);
        k_zero_f<<<320, 256>>>(agg, NN * Out);
        k_scatter<<<1024, 256>>>(ei, gh, Out);
        k_zero_f<<<2, 256>>>(cs1, Out);
        k_zero_f<<<2, 256>>>(cs2, Out);
        k_act_stats<<<512, 256>>>(gB[l], Out);
        k_bn<<<512, 256>>>(bufs[l & 1], Out);
        xcur = bufs[l & 1];
    }

    // ---- pool + FC head ----
    k_pool_fc<<<1, 256>>>(xcur, gender, handed,
                          (const float*)d_in[24], (const float*)d_in[25],
                          (const float*)d_in[26], (const float*)d_in[27],
                          (const float*)d_in[28], (const float*)d_in[29],
                          (float*)d_out);
}

// round 12
// speedup vs baseline: 3.4552x; 3.4552x over previous
#include <cuda_runtime.h>
#include <math.h>

#define NN    1024      // nodes / seq len
#define NE    16384     // edges
#define BSZ   16
#define LEN0  8500
#define HH    640
#define G4    2560      // 4*H
#define TT    1024
#define SB    128       // scan blocks (<= #SMs for co-residency)

// ---------------- device scratch (no allocations allowed) ----------------
__device__ float g_xw[TT * G4];        // 10.5 MB input projection
__device__ float g_seqA[TT * HH];
__device__ float g_seqB[TT * HH];
__device__ __align__(16) float g_hbuf[2 * HH];   // double-buffered h
__device__ int   g_ctr[TT];            // per-step arrival counters
__device__ int   g_rel;                // central release word (CTA0 -> all)
__device__ float g_gh[NN * 320];       // gcn xW
__device__ float g_agg[NN * 320];      // gcn aggregation
__device__ float g_deg[NN];
__device__ float g_dinv[NN];
__device__ float g_cs1[320];           // column sums
__device__ float g_cs2[320];           // column sums of squares

// ---------------- utility ----------------
__global__ void k_zero_f(float* p, int n) {
    int st = gridDim.x * blockDim.x;
    for (int i = blockIdx.x * blockDim.x + threadIdx.x; i < n; i += st) p[i] = 0.f;
}
__global__ void k_zero_ctr() {
    int i = blockIdx.x * blockDim.x + threadIdx.x;
    if (i < TT) g_ctr[i] = 0;
    if (i == 0) g_rel = 0;
}

// ---------------- SGEMM  C[M,N] = A[M,K] * B[N,K]^T + b0[n] + b1[n] ----------------
// BM=64, BN=128, BK=8, 256 threads, 4x8 microtile, double-buffered smem.
// Requires M%64==0, N%128==0, K%4==0 (rows 16B aligned). K tail guarded.
__global__ void __launch_bounds__(256, 3) k_gemm_nt(
    const float* __restrict__ A, const float* __restrict__ B,
    const float* __restrict__ b0, const float* __restrict__ b1,
    float* __restrict__ C, int M, int N, int K)
{
    __shared__ __align__(16) float As[2][8][68];
    __shared__ __align__(16) float Bs[2][8][132];
    const int tid = threadIdx.x;
    const int bm = blockIdx.y * 64;
    const int bn = blockIdx.x * 128;
    const int ty = tid >> 4, tx = tid & 15;      // 16x16 thread grid
    const int arow = tid >> 2, ak = (tid & 3) * 2;   // A loader: float2
    const int brow = tid >> 1, bk = (tid & 1) * 4;   // B loader: float4
    const float* Ap = A + (size_t)(bm + arow) * K;
    const float* Bp = B + (size_t)(bn + brow) * K;

    float acc[4][8];
    #pragma unroll
    for (int i = 0; i < 4; i++)
        #pragma unroll
        for (int j = 0; j < 8; j++) acc[i][j] = 0.f;

    // prologue: tile 0 -> buffer 0  (K >= 8 always here; guards still applied)
    {
        float2 av = (ak < K) ? *(const float2*)&Ap[ak] : make_float2(0.f, 0.f);
        float4 bv = (bk < K) ? *(const float4*)&Bp[bk] : make_float4(0.f, 0.f, 0.f, 0.f);
        As[0][ak + 0][arow] = av.x; As[0][ak + 1][arow] = av.y;
        Bs[0][bk + 0][brow] = bv.x; Bs[0][bk + 1][brow] = bv.y;
        Bs[0][bk + 2][brow] = bv.z; Bs[0][bk + 3][brow] = bv.w;
    }
    __syncthreads();

    int buf = 0;
    for (int k0 = 0; k0 < K; k0 += 8) {
        const bool more = (k0 + 8 < K);
        float2 av = make_float2(0.f, 0.f);
        float4 bv = make_float4(0.f, 0.f, 0.f, 0.f);
        if (more) {
            int ka = k0 + 8 + ak;
            int kb = k0 + 8 + bk;
            if (ka < K) av = *(const float2*)&Ap[ka];   // K even -> both lanes in range
            if (kb < K) bv = *(const float4*)&Bp[kb];   // K%4==0 -> whole vec in range
        }
        #pragma unroll
        for (int kk = 0; kk < 8; kk++) {
            float4 a0 = *(const float4*)&As[buf][kk][ty * 4];
            float4 r0 = *(const float4*)&Bs[buf][kk][tx * 8];
            float4 r1 = *(const float4*)&Bs[buf][kk][tx * 8 + 4];
            float ra[4] = {a0.x, a0.y, a0.z, a0.w};
            float rb[8] = {r0.x, r0.y, r0.z, r0.w, r1.x, r1.y, r1.z, r1.w};
            #pragma unroll
            for (int i = 0; i < 4; i++)
                #pragma unroll
                for (int j = 0; j < 8; j++)
                    acc[i][j] += ra[i] * rb[j];
        }
        if (more) {
            int nb2 = buf ^ 1;
            As[nb2][ak + 0][arow] = av.x; As[nb2][ak + 1][arow] = av.y;
            Bs[nb2][bk + 0][brow] = bv.x; Bs[nb2][bk + 1][brow] = bv.y;
            Bs[nb2][bk + 2][brow] = bv.z; Bs[nb2][bk + 3][brow] = bv.w;
            __syncthreads();
            buf = nb2;
        }
    }
    #pragma unroll
    for (int i = 0; i < 4; i++) {
        int m = bm + ty * 4 + i;
        int n0 = bn + tx * 8;
        #pragma unroll
        for (int j = 0; j < 8; j++) {
            int n = n0 + j;
            C[(size_t)m * N + n] = acc[i][j] + b0[n] + b1[n];
        }
    }
}

// ---------------- GEMM NN for GCN:  C[1024,N] = A[1024,K] * B[K,N] ----------------
__global__ void __launch_bounds__(256) k_gemm_nn(
    const float* __restrict__ A, const float* __restrict__ B,
    float* __restrict__ C, int N, int K)
{
    __shared__ float As[8][64];
    __shared__ float Bs[8][64];
    const int tid = threadIdx.x;
    const int bm = blockIdx.y * 64;
    const int bn = blockIdx.x * 64;
    const int ty = tid >> 4, tx = tid & 15;
    const int arow = tid >> 2, ak = (tid & 3) * 2;
    const int bkr = tid >> 5, bc = (tid & 31) * 2;
    float acc[4][4] = {};
    for (int k0 = 0; k0 < K; k0 += 8) {
        #pragma unroll
        for (int i = 0; i < 2; i++) {
            int kk = k0 + ak + i;
            As[ak + i][arow] = (kk < K) ? A[(bm + arow) * K + kk] : 0.f;
        }
        #pragma unroll
        for (int i = 0; i < 2; i++) {
            int n = bn + bc + i;
            Bs[bkr][bc + i] = (k0 + bkr < K && n < N) ? B[(k0 + bkr) * N + n] : 0.f;
        }
        __syncthreads();
        #pragma unroll
        for (int kk = 0; kk < 8; kk++) {
            float ra[4], rb[4];
            #pragma unroll
            for (int i = 0; i < 4; i++) ra[i] = As[kk][ty * 4 + i];
            #pragma unroll
            for (int j = 0; j < 4; j++) rb[j] = Bs[kk][tx * 4 + j];
            #pragma unroll
            for (int i = 0; i < 4; i++)
                #pragma unroll
                for (int j = 0; j < 4; j++)
                    acc[i][j] += ra[i] * rb[j];
        }
        __syncthreads();
    }
    #pragma unroll
    for (int i = 0; i < 4; i++) {
        int m = bm + ty * 4 + i;
        #pragma unroll
        for (int j = 0; j < 4; j++) {
            int n = bn + tx * 4 + j;
            if (n < N) C[m * N + n] = acc[i][j];
        }
    }
}

// ---------------- LSTM recurrent scan ----------------
// 128 blocks x 160 threads. Warp w of block b owns element j = 5b+w; all four
// Whh gate rows live in registers (20 float4 per thread).
// Barrier: per-step atomic counter + CENTRAL RELEASE. Every CTA's tid0 does one
// atomicAdd; only CTA0's tid0 polls the counter, then publishes t+1 to g_rel;
// the other 127 CTAs poll g_rel (single writer line, 1 poller thread per CTA).
__global__ void __launch_bounds__(160) k_lstm_scan(
    const float* __restrict__ xw,    // [T, 4H]
    const float* __restrict__ Whh,   // [4H, H]
    float* __restrict__ out)         // [T, H]
{
    __shared__ __align__(16) float h_s[HH];
    const int tid  = threadIdx.x;
    const int wid  = tid >> 5;
    const int lane = tid & 31;
    const int j    = blockIdx.x * 5 + wid;

    // weight layout: w?[k4] covers h indices [4*lane + 128*k4, +4)
    float4 wI[5], wF[5], wG[5], wO[5];
    #pragma unroll
    for (int k4 = 0; k4 < 5; k4++) {
        int off = 4 * lane + 128 * k4;
        wI[k4] = *(const float4*)&Whh[(size_t)(0 * HH + j) * HH + off];
        wF[k4] = *(const float4*)&Whh[(size_t)(1 * HH + j) * HH + off];
        wG[k4] = *(const float4*)&Whh[(size_t)(2 * HH + j) * HH + off];
        wO[k4] = *(const float4*)&Whh[(size_t)(3 * HH + j) * HH + off];
    }
    #pragma unroll
    for (int i = 0; i < 4; i++) h_s[tid + 160 * i] = 0.f;
    float c = 0.f;                 // live in lane 0 of each warp
    float xwv = (lane < 4) ? __ldg(&xw[lane * HH + j]) : 0.f;
    __syncthreads();

    for (int t = 0; t < TT; t++) {
        float aI = 0.f, aF = 0.f, aG = 0.f, aO = 0.f;
        #pragma unroll
        for (int k4 = 0; k4 < 5; k4++) {
            float4 hv = *(const float4*)&h_s[4 * lane + 128 * k4];
            aI += wI[k4].x * hv.x + wI[k4].y * hv.y + wI[k4].z * hv.z + wI[k4].w * hv.w;
            aF += wF[k4].x * hv.x + wF[k4].y * hv.y + wF[k4].z * hv.z + wF[k4].w * hv.w;
            aG += wG[k4].x * hv.x + wG[k4].y * hv.y + wG[k4].z * hv.z + wG[k4].w * hv.w;
            aO += wO[k4].x * hv.x + wO[k4].y * hv.y + wO[k4].z * hv.z + wO[k4].w * hv.w;
        }
        #pragma unroll
        for (int off = 16; off; off >>= 1) {
            aI += __shfl_down_sync(0xffffffffu, aI, off);
            aF += __shfl_down_sync(0xffffffffu, aF, off);
            aG += __shfl_down_sync(0xffffffffu, aG, off);
            aO += __shfl_down_sync(0xffffffffu, aO, off);
        }
        float xI = __shfl_sync(0xffffffffu, xwv, 0);
        float xF = __shfl_sync(0xffffffffu, xwv, 1);
        float xG = __shfl_sync(0xffffffffu, xwv, 2);
        float xO = __shfl_sync(0xffffffffu, xwv, 3);

        const int nb = (t + 1) & 1;
        if (lane == 0) {
            float iv = __fdividef(1.f, 1.f + __expf(-(aI + xI)));
            float fv = __fdividef(1.f, 1.f + __expf(-(aF + xF)));
            float gv = 1.f - __fdividef(2.f, 1.f + __expf(2.f * (aG + xG)));
            float ov = __fdividef(1.f, 1.f + __expf(-(aO + xO)));
            c = fv * c + iv * gv;
            float hv = ov * (1.f - __fdividef(2.f, 1.f + __expf(2.f * c)));
            out[t * HH + j] = hv;
            g_hbuf[nb * HH + j] = hv;
        }
        // prefetch next step's xw while the barrier drains
        float xnext = 0.f;
        if (lane < 4 && t + 1 < TT) xnext = __ldg(&xw[(size_t)(t + 1) * G4 + lane * HH + j]);

        __syncthreads();                   // this CTA's h writes done
        if (tid == 0) {
            __threadfence();               // publish h (release-cumulative)
            atomicAdd(&g_ctr[t], 1);
            if (blockIdx.x == 0) {
                while (*((volatile int*)&g_ctr[t]) < SB) { }
                __threadfence();
                *((volatile int*)&g_rel) = t + 1;   // central release
            } else {
                while (*((volatile int*)&g_rel) < t + 1) { }
            }
            __threadfence();               // acquire
        }
        __syncthreads();                   // all CTAs published h(t+1)
        ((float4*)h_s)[tid] = ((const float4*)&g_hbuf[nb * HH])[tid];
        __syncthreads();                   // h_s ready for next step
        xwv = xnext;
    }
}

// ---------------- GCN helpers ----------------
__global__ void k_deg_count(const int* __restrict__ ei) {
    int e = blockIdx.x * blockDim.x + threadIdx.x;
    if (e < NE) atomicAdd(&g_deg[ei[NE + e]], 1.f);
}
__global__ void k_deg_fin() {
    int i = blockIdx.x * blockDim.x + threadIdx.x;
    if (i < NN) g_dinv[i] = rsqrtf(g_deg[i] + 1.f);   // +1 self loop
}
__global__ void k_scatter(const int* __restrict__ ei, const float* __restrict__ h, int N) {
    int total = (NE + NN) * N;
    int st = gridDim.x * blockDim.x;
    for (int idx = blockIdx.x * blockDim.x + threadIdx.x; idx < total; idx += st) {
        int e = idx / N, cidx = idx - e * N;
        int s, d;
        if (e < NE) { s = ei[e]; d = ei[NE + e]; }
        else        { s = e - NE; d = s; }
        atomicAdd(&g_agg[d * N + cidx], g_dinv[s] * g_dinv[d] * h[s * N + cidx]);
    }
}
__global__ void k_act_stats(const float* __restrict__ b, int N) {
    int total = NN * N;
    int st = gridDim.x * blockDim.x;
    for (int idx = blockIdx.x * blockDim.x + threadIdx.x; idx < total; idx += st) {
        int cidx = idx % N;
        float v = g_agg[idx] + b[cidx];
        v = (v > 0.f) ? v : 0.01f * v;     // leaky_relu slope 0.01
        g_agg[idx] = v;
        atomicAdd(&g_cs1[cidx], v);
        atomicAdd(&g_cs2[cidx], v * v);
    }
}
__global__ void k_bn(float* __restrict__ xout, int N) {
    const float inv = 1.f / (float)NN;
    int total = NN * N;
    int st = gridDim.x * blockDim.x;
    for (int idx = blockIdx.x * blockDim.x + threadIdx.x; idx < total; idx += st) {
        int cidx = idx % N;
        float m  = g_cs1[cidx] * inv;
        float vr = g_cs2[cidx] * inv - m * m;       // biased variance
        xout[idx] = (g_agg[idx] - m) * rsqrtf(vr + 1e-5f);
    }
}

// ---------------- segment-sum pool + FC head (single block) ----------------
__global__ void __launch_bounds__(256) k_pool_fc(
    const float* __restrict__ x,            // [1024, 50]
    const float* __restrict__ gender, const float* __restrict__ handed,
    const float* __restrict__ W1, const float* __restrict__ b1,   // [32,52],[32]
    const float* __restrict__ W2, const float* __restrict__ b2,   // [16,32],[16]
    const float* __restrict__ W3, const float* __restrict__ b3,   // [1,16],[1]
    float* __restrict__ outp)
{
    __shared__ float xp[16][52];
    __shared__ float y1[16][32];
    __shared__ float y2[16][16];
    int tid = threadIdx.x;
    for (int idx = tid; idx < 16 * 50; idx += 256) {
        int bb = idx / 50, cc = idx % 50;
        float s = 0.f;
        for (int r = 0; r < 64; r++) s += x[(bb * 64 + r) * 50 + cc];
        xp[bb][cc] = s;
    }
    if (tid < 16) { xp[tid][50] = gender[tid]; xp[tid][51] = handed[tid]; }
    __syncthreads();
    for (int idx = tid; idx < 16 * 32; idx += 256) {
        int bb = idx >> 5, o = idx & 31;
        float s = b1[o];
        for (int k = 0; k < 52; k++) s += xp[bb][k] * W1[o * 52 + k];
        y1[bb][o] = s;
    }
    __syncthreads();
    {
        int bb = tid >> 4, o = tid & 15;
        float s = b2[o];
        for (int k = 0; k < 32; k++) s += y1[bb][k] * W2[o * 32 + k];
        y2[bb][o] = s;
    }
    __syncthreads();
    if (tid < 16) {
        float s = b3[0];
        for (int k = 0; k < 16; k++) s += y2[tid][k] * W3[k];
        outp[tid] = s;
    }
}

// ---------------- orchestration ----------------
extern "C" void kernel_launch(void* const* d_in, const int* in_sizes, int n_in,
                              void* d_out, int out_size)
{
    const float* x_in   = (const float*)d_in[0];
    const int*   ei     = (const int*)  d_in[1];
    const float* gender = (const float*)d_in[2];
    const float* handed = (const float*)d_in[3];
    const float* Wih[3] = {(const float*)d_in[4],  (const float*)d_in[8],  (const float*)d_in[12]};
    const float* Whh[3] = {(const float*)d_in[5],  (const float*)d_in[9],  (const float*)d_in[13]};
    const float* bih[3] = {(const float*)d_in[6],  (const float*)d_in[10], (const float*)d_in[14]};
    const float* bhh[3] = {(const float*)d_in[7],  (const float*)d_in[11], (const float*)d_in[15]};
    const float* gW[4]  = {(const float*)d_in[16], (const float*)d_in[18], (const float*)d_in[20], (const float*)d_in[22]};
    const float* gB[4]  = {(const float*)d_in[17], (const float*)d_in[19], (const float*)d_in[21], (const float*)d_in[23]};

    float *xw, *seqA, *seqB, *gh, *agg, *deg, *cs1, *cs2;
    cudaGetSymbolAddress((void**)&xw,   g_xw);
    cudaGetSymbolAddress((void**)&seqA, g_seqA);
    cudaGetSymbolAddress((void**)&seqB, g_seqB);
    cudaGetSymbolAddress((void**)&gh,   g_gh);
    cudaGetSymbolAddress((void**)&agg,  g_agg);
    cudaGetSymbolAddress((void**)&deg,  g_deg);
    cudaGetSymbolAddress((void**)&cs1,  g_cs1);
    cudaGetSymbolAddress((void**)&cs2,  g_cs2);
    (void)in_sizes; (void)n_in; (void)out_size;

    dim3 gemmGrid(G4 / 128, TT / 64);   // (20, 16) = 320 CTAs

    // ---- LSTM layer 0 ----
    k_gemm_nt<<<gemmGrid, 256>>>(x_in, Wih[0], bih[0], bhh[0], xw, TT, G4, LEN0);
    k_zero_ctr<<<4, 256>>>();
    k_lstm_scan<<<SB, 160>>>(xw, Whh[0], seqA);
    // ---- LSTM layer 1 ----
    k_gemm_nt<<<gemmGrid, 256>>>(seqA, Wih[1], bih[1], bhh[1], xw, TT, G4, HH);
    k_zero_ctr<<<4, 256>>>();
    k_lstm_scan<<<SB, 160>>>(xw, Whh[1], seqB);
    // ---- LSTM layer 2 ----
    k_gemm_nt<<<gemmGrid, 256>>>(seqB, Wih[2], bih[2], bhh[2], xw, TT, G4, HH);
    k_zero_ctr<<<4, 256>>>();
    k_lstm_scan<<<SB, 160>>>(xw, Whh[2], seqA);

    // ---- degrees / symmetric norm ----
    k_zero_f<<<4, 256>>>(deg, NN);
    k_deg_count<<<64, 256>>>(ei);
    k_deg_fin<<<4, 256>>>();

    // ---- 4 GCN layers ----
    int dims[5] = {HH, 320, 180, 90, 50};
    const float* xcur = seqA;
    float* bufs[2] = {seqB, seqA};
    for (int l = 0; l < 4; l++) {
        int In = dims[l], Out = dims[l + 1];
        k_gemm_nn<<<dim3((Out + 63) / 64, NN / 64), 256>>>(xcur, gW[l], gh, Out, In);
        k_zero_f<<<320, 256>>>(agg, NN * Out);
        k_scatter<<<1024, 256>>>(ei, gh, Out);
        k_zero_f<<<2, 256>>>(cs1, Out);
        k_zero_f<<<2, 256>>>(cs2, Out);
        k_act_stats<<<512, 256>>>(gB[l], Out);
        k_bn<<<512, 256>>>(bufs[l & 1], Out);
        xcur = bufs[l & 1];
    }

    // ---- pool + FC head ----
    k_pool_fc<<<1, 256>>>(xcur, gender, handed,
                          (const float*)d_in[24], (const float*)d_in[25],
                          (const float*)d_in[26], (const float*)d_in[27],
                          (const float*)d_in[28], (const float*)d_in[29],
                          (float*)d_out);
}

// round 14
// speedup vs baseline: 4.0830x; 1.1817x over previous
#include <cuda_runtime.h>
#include <math.h>

#define NN    1024      // nodes / seq len
#define NE    16384     // edges
#define BSZ   16
#define LEN0  8500
#define HH    640
#define G4    2560      // 4*H
#define TT    1024
#define SB    128       // scan blocks (<= #SMs for co-residency)

// ---------------- device scratch (no allocations allowed) ----------------
__device__ float g_xw[TT * G4];        // 10.5 MB final input projection
__device__ float g_p0[TT * G4];        // split-K partial 0
__device__ float g_p1[TT * G4];        // split-K partial 1
__device__ float g_seqA[TT * HH];
__device__ float g_seqB[TT * HH];
__device__ __align__(16) float g_hbuf[2 * HH];   // double-buffered h
__device__ int   g_ctr[TT];            // per-step arrival counters
__device__ int   g_rel;                // release word (last arriver -> all)
__device__ float g_gh[NN * 320];       // gcn xW
__device__ float g_agg[NN * 320];      // gcn aggregation
__device__ float g_deg[NN];
__device__ float g_dinv[NN];
__device__ float g_cs1[320];           // column sums
__device__ float g_cs2[320];           // column sums of squares

// ---------------- acquire/release primitives ----------------
__device__ __forceinline__ int atom_add_acqrel(int* p, int v) {
    int old;
    asm volatile("atom.acq_rel.gpu.add.s32 %0, [%1], %2;"
                 : "=r"(old) : "l"(p), "r"(v) : "memory");
    return old;
}
__device__ __forceinline__ void st_release(int* p, int v) {
    asm volatile("st.release.gpu.s32 [%0], %1;" :: "l"(p), "r"(v) : "memory");
}
__device__ __forceinline__ int ld_acquire(int* p) {
    int v;
    asm volatile("ld.acquire.gpu.s32 %0, [%1];" : "=r"(v) : "l"(p) : "memory");
    return v;
}

// ---------------- utility ----------------
__global__ void k_zero_f(float* p, int n) {
    int st = gridDim.x * blockDim.x;
    for (int i = blockIdx.x * blockDim.x + threadIdx.x; i < n; i += st) p[i] = 0.f;
}
__global__ void k_zero_ctr() {
    int i = blockIdx.x * blockDim.x + threadIdx.x;
    if (i < TT) g_ctr[i] = 0;
    if (i == 0) g_rel = 0;
}

// ---------------- split-K SGEMM:  P_z = A[:, zKh:] * B[:, zKh:]^T ----------------
// BM=128, BN=128, BK=8, 256 threads, 8x8 microtile, double-buffered smem.
// M%128==0, N%128==0, K%4==0, Kh%4==0. Slice tail (len%8==4) zero-padded.
__global__ void __launch_bounds__(256, 2) k_gemm_nt_sk(
    const float* __restrict__ A, const float* __restrict__ B,
    float* __restrict__ P0, float* __restrict__ P1,
    int M, int N, int K, int Kh)
{
    __shared__ __align__(16) float As[2][8][132];
    __shared__ __align__(16) float Bs[2][8][132];
    const int z  = blockIdx.z;
    const int ks = z * Kh;
    const int Kl = min(K - ks, Kh);                 // slice length, %4==0
    float* __restrict__ P = z ? P1 : P0;
    const int tid = threadIdx.x;
    const int bm = blockIdx.y * 128;
    const int bn = blockIdx.x * 128;
    const int ty = tid >> 4, tx = tid & 15;         // 16x16 thread grid
    const int row = tid >> 1;                       // 0..127 loader row
    const int kq  = (tid & 1) * 4;                  // 0 or 4
    const float* Ap = A + (size_t)(bm + row) * K + ks;
    const float* Bp = B + (size_t)(bn + row) * K + ks;

    float acc[8][8];
    #pragma unroll
    for (int i = 0; i < 8; i++)
        #pragma unroll
        for (int j = 0; j < 8; j++) acc[i][j] = 0.f;

    // prologue: tile 0 -> buffer 0
    {
        float4 av = make_float4(0.f,0.f,0.f,0.f), bv = make_float4(0.f,0.f,0.f,0.f);
        if (kq < Kl) { av = *(const float4*)&Ap[kq]; bv = *(const float4*)&Bp[kq]; }
        As[0][kq+0][row] = av.x; As[0][kq+1][row] = av.y;
        As[0][kq+2][row] = av.z; As[0][kq+3][row] = av.w;
        Bs[0][kq+0][row] = bv.x; Bs[0][kq+1][row] = bv.y;
        Bs[0][kq+2][row] = bv.z; Bs[0][kq+3][row] = bv.w;
    }
    __syncthreads();

    int buf = 0;
    for (int k0 = 0; k0 < Kl; k0 += 8) {
        const bool more = (k0 + 8 < Kl);
        float4 av = make_float4(0.f,0.f,0.f,0.f), bv = make_float4(0.f,0.f,0.f,0.f);
        if (more) {
            int kk2 = k0 + 8 + kq;
            if (kk2 < Kl) { av = *(const float4*)&Ap[kk2]; bv = *(const float4*)&Bp[kk2]; }
        }
        #pragma unroll
        for (int kk = 0; kk < 8; kk++) {
            float4 a0 = *(const float4*)&As[buf][kk][ty * 8];
            float4 a1 = *(const float4*)&As[buf][kk][ty * 8 + 4];
            float4 r0 = *(const float4*)&Bs[buf][kk][tx * 8];
            float4 r1 = *(const float4*)&Bs[buf][kk][tx * 8 + 4];
            float ra[8] = {a0.x, a0.y, a0.z, a0.w, a1.x, a1.y, a1.z, a1.w};
            float rb[8] = {r0.x, r0.y, r0.z, r0.w, r1.x, r1.y, r1.z, r1.w};
            #pragma unroll
            for (int i = 0; i < 8; i++)
                #pragma unroll
                for (int j = 0; j < 8; j++)
                    acc[i][j] += ra[i] * rb[j];
        }
        if (more) {
            int nb2 = buf ^ 1;
            As[nb2][kq+0][row] = av.x; As[nb2][kq+1][row] = av.y;
            As[nb2][kq+2][row] = av.z; As[nb2][kq+3][row] = av.w;
            Bs[nb2][kq+0][row] = bv.x; Bs[nb2][kq+1][row] = bv.y;
            Bs[nb2][kq+2][row] = bv.z; Bs[nb2][kq+3][row] = bv.w;
            __syncthreads();
            buf = nb2;
        }
    }
    #pragma unroll
    for (int i = 0; i < 8; i++) {
        size_t m = bm + ty * 8 + i;
        int n0 = bn + tx * 8;
        #pragma unroll
        for (int j = 0; j < 8; j++)
            P[m * N + n0 + j] = acc[i][j];
    }
}

// combine split-K partials + both biases
__global__ void k_combine(const float* __restrict__ P0, const float* __restrict__ P1,
                          const float* __restrict__ b0, const float* __restrict__ b1,
                          float* __restrict__ C, int total, int N)
{
    int st = gridDim.x * blockDim.x;
    for (int i = blockIdx.x * blockDim.x + threadIdx.x; i < total; i += st) {
        int n = i % N;
        C[i] = P0[i] + P1[i] + b0[n] + b1[n];
    }
}

// ---------------- GEMM NN for GCN:  C[1024,N] = A[1024,K] * B[K,N] ----------------
__global__ void __launch_bounds__(256) k_gemm_nn(
    const float* __restrict__ A, const float* __restrict__ B,
    float* __restrict__ C, int N, int K)
{
    __shared__ float As[8][64];
    __shared__ float Bs[8][64];
    const int tid = threadIdx.x;
    const int bm = blockIdx.y * 64;
    const int bn = blockIdx.x * 64;
    const int ty = tid >> 4, tx = tid & 15;
    const int arow = tid >> 2, ak = (tid & 3) * 2;
    const int bkr = tid >> 5, bc = (tid & 31) * 2;
    float acc[4][4] = {};
    for (int k0 = 0; k0 < K; k0 += 8) {
        #pragma unroll
        for (int i = 0; i < 2; i++) {
            int kk = k0 + ak + i;
            As[ak + i][arow] = (kk < K) ? A[(bm + arow) * K + kk] : 0.f;
        }
        #pragma unroll
        for (int i = 0; i < 2; i++) {
            int n = bn + bc + i;
            Bs[bkr][bc + i] = (k0 + bkr < K && n < N) ? B[(k0 + bkr) * N + n] : 0.f;
        }
        __syncthreads();
        #pragma unroll
        for (int kk = 0; kk < 8; kk++) {
            float ra[4], rb[4];
            #pragma unroll
            for (int i = 0; i < 4; i++) ra[i] = As[kk][ty * 4 + i];
            #pragma unroll
            for (int j = 0; j < 4; j++) rb[j] = Bs[kk][tx * 4 + j];
            #pragma unroll
            for (int i = 0; i < 4; i++)
                #pragma unroll
                for (int j = 0; j < 4; j++)
                    acc[i][j] += ra[i] * rb[j];
        }
        __syncthreads();
    }
    #pragma unroll
    for (int i = 0; i < 4; i++) {
        int m = bm + ty * 4 + i;
        #pragma unroll
        for (int j = 0; j < 4; j++) {
            int n = bn + tx * 4 + j;
            if (n < N) C[m * N + n] = acc[i][j];
        }
    }
}

// ---------------- LSTM recurrent scan ----------------
// 128 blocks x 160 threads; warp w owns element j = 5b+w, Whh rows in regs.
// Barrier: single acq_rel atomic arrival; the LAST arriver (old==SB-1) does the
// release store; others spin on ld.acquire. No MEMBARs, no central poller.
__global__ void __launch_bounds__(160) k_lstm_scan(
    const float* __restrict__ xw,    // [T, 4H]
    const float* __restrict__ Whh,   // [4H, H]
    float* __restrict__ out)         // [T, H]
{
    __shared__ __align__(16) float h_s[HH];
    const int tid  = threadIdx.x;
    const int wid  = tid >> 5;
    const int lane = tid & 31;
    const int j    = blockIdx.x * 5 + wid;

    float4 wI[5], wF[5], wG[5], wO[5];
    #pragma unroll
    for (int k4 = 0; k4 < 5; k4++) {
        int off = 4 * lane + 128 * k4;
        wI[k4] = *(const float4*)&Whh[(size_t)(0 * HH + j) * HH + off];
        wF[k4] = *(const float4*)&Whh[(size_t)(1 * HH + j) * HH + off];
        wG[k4] = *(const float4*)&Whh[(size_t)(2 * HH + j) * HH + off];
        wO[k4] = *(const float4*)&Whh[(size_t)(3 * HH + j) * HH + off];
    }
    #pragma unroll
    for (int i = 0; i < 4; i++) h_s[tid + 160 * i] = 0.f;
    float c = 0.f;                 // live in lane 0 of each warp
    float xwv = (lane < 4) ? __ldg(&xw[lane * HH + j]) : 0.f;
    __syncthreads();

    for (int t = 0; t < TT; t++) {
        float aI = 0.f, aF = 0.f, aG = 0.f, aO = 0.f;
        #pragma unroll
        for (int k4 = 0; k4 < 5; k4++) {
            float4 hv = *(const float4*)&h_s[4 * lane + 128 * k4];
            aI += wI[k4].x * hv.x + wI[k4].y * hv.y + wI[k4].z * hv.z + wI[k4].w * hv.w;
            aF += wF[k4].x * hv.x + wF[k4].y * hv.y + wF[k4].z * hv.z + wF[k4].w * hv.w;
            aG += wG[k4].x * hv.x + wG[k4].y * hv.y + wG[k4].z * hv.z + wG[k4].w * hv.w;
            aO += wO[k4].x * hv.x + wO[k4].y * hv.y + wO[k4].z * hv.z + wO[k4].w * hv.w;
        }
        #pragma unroll
        for (int off = 16; off; off >>= 1) {
            aI += __shfl_down_sync(0xffffffffu, aI, off);
            aF += __shfl_down_sync(0xffffffffu, aF, off);
            aG += __shfl_down_sync(0xffffffffu, aG, off);
            aO += __shfl_down_sync(0xffffffffu, aO, off);
        }
        float xI = __shfl_sync(0xffffffffu, xwv, 0);
        float xF = __shfl_sync(0xffffffffu, xwv, 1);
        float xG = __shfl_sync(0xffffffffu, xwv, 2);
        float xO = __shfl_sync(0xffffffffu, xwv, 3);

        const int nb = (t + 1) & 1;
        if (lane == 0) {
            float iv = __fdividef(1.f, 1.f + __expf(-(aI + xI)));
            float fv = __fdividef(1.f, 1.f + __expf(-(aF + xF)));
            float gv = 1.f - __fdividef(2.f, 1.f + __expf(2.f * (aG + xG)));
            float ov = __fdividef(1.f, 1.f + __expf(-(aO + xO)));
            c = fv * c + iv * gv;
            float hv = ov * (1.f - __fdividef(2.f, 1.f + __expf(2.f * c)));
            out[t * HH + j] = hv;
            g_hbuf[nb * HH + j] = hv;
        }
        // prefetch next step's xw while the barrier drains
        float xnext = 0.f;
        if (lane < 4 && t + 1 < TT) xnext = __ldg(&xw[(size_t)(t + 1) * G4 + lane * HH + j]);

        __syncthreads();                   // this CTA's h writes done
        if (tid == 0) {
            int old = atom_add_acqrel(&g_ctr[t], 1);
            if (old == SB - 1) {
                st_release(&g_rel, t + 1);           // last arriver releases
            } else {
                while (ld_acquire(&g_rel) < t + 1) { }
            }
        }
        __syncthreads();                   // all CTAs published h(t+1)
        ((float4*)h_s)[tid] = ((const float4*)&g_hbuf[nb * HH])[tid];
        __syncthreads();                   // h_s ready for next step
        xwv = xnext;
    }
}

// ---------------- GCN helpers ----------------
__global__ void k_deg_count(const int* __restrict__ ei) {
    int e = blockIdx.x * blockDim.x + threadIdx.x;
    if (e < NE) atomicAdd(&g_deg[ei[NE + e]], 1.f);
}
__global__ void k_deg_fin() {
    int i = blockIdx.x * blockDim.x + threadIdx.x;
    if (i < NN) g_dinv[i] = rsqrtf(g_deg[i] + 1.f);   // +1 self loop
}
// warp-per-edge scatter: lanes cover columns (no integer division)
__global__ void k_scatter(const int* __restrict__ ei, const float* __restrict__ h, int N) {
    int w = (blockIdx.x * blockDim.x + threadIdx.x) >> 5;
    int lane = threadIdx.x & 31;
    if (w >= NE + NN) return;
    int s, d;
    if (w < NE) { s = ei[w]; d = ei[NE + w]; }
    else        { s = w - NE; d = s; }
    float nrm = g_dinv[s] * g_dinv[d];
    const float* hr = h + (size_t)s * N;
    float* ar = g_agg + (size_t)d * N;
    for (int cx = lane; cx < N; cx += 32)
        atomicAdd(&ar[cx], nrm * hr[cx]);
}
// row-per-block activation + stats (no division)
__global__ void k_act_stats(const float* __restrict__ b, int N) {
    int rowb = blockIdx.x;               // 0..NN-1
    float* ar = g_agg + (size_t)rowb * N;
    for (int cx = threadIdx.x; cx < N; cx += blockDim.x) {
        float v = ar[cx] + b[cx];
        v = (v > 0.f) ? v : 0.01f * v;   // leaky_relu slope 0.01
        ar[cx] = v;
        atomicAdd(&g_cs1[cx], v);
        atomicAdd(&g_cs2[cx], v * v);
    }
}
__global__ void k_bn(float* __restrict__ xout, int N) {
    const float inv = 1.f / (float)NN;
    int rowb = blockIdx.x;
    const float* ar = g_agg + (size_t)rowb * N;
    float* xr = xout + (size_t)rowb * N;
    for (int cx = threadIdx.x; cx < N; cx += blockDim.x) {
        float m  = g_cs1[cx] * inv;
        float vr = g_cs2[cx] * inv - m * m;           // biased variance
        xr[cx] = (ar[cx] - m) * rsqrtf(vr + 1e-5f);
    }
}

// ---------------- segment-sum pool + FC head (single block) ----------------
__global__ void __launch_bounds__(256) k_pool_fc(
    const float* __restrict__ x,            // [1024, 50]
    const float* __restrict__ gender, const float* __restrict__ handed,
    const float* __restrict__ W1, const float* __restrict__ b1,   // [32,52],[32]
    const float* __restrict__ W2, const float* __restrict__ b2,   // [16,32],[16]
    const float* __restrict__ W3, const float* __restrict__ b3,   // [1,16],[1]
    float* __restrict__ outp)
{
    __shared__ float xp[16][52];
    __shared__ float y1[16][32];
    __shared__ float y2[16][16];
    int tid = threadIdx.x;
    for (int idx = tid; idx < 16 * 50; idx += 256) {
        int bb = idx / 50, cc = idx % 50;
        float s = 0.f;
        for (int r = 0; r < 64; r++) s += x[(bb * 64 + r) * 50 + cc];
        xp[bb][cc] = s;
    }
    if (tid < 16) { xp[tid][50] = gender[tid]; xp[tid][51] = handed[tid]; }
    __syncthreads();
    for (int idx = tid; idx < 16 * 32; idx += 256) {
        int bb = idx >> 5, o = idx & 31;
        float s = b1[o];
        for (int k = 0; k < 52; k++) s += xp[bb][k] * W1[o * 52 + k];
        y1[bb][o] = s;
    }
    __syncthreads();
    {
        int bb = tid >> 4, o = tid & 15;
        float s = b2[o];
        for (int k = 0; k < 32; k++) s += y1[bb][k] * W2[o * 32 + k];
        y2[bb][o] = s;
    }
    __syncthreads();
    if (tid < 16) {
        float s = b3[0];
        for (int k = 0; k < 16; k++) s += y2[tid][k] * W3[k];
        outp[tid] = s;
    }
}

// ---------------- orchestration ----------------
extern "C" void kernel_launch(void* const* d_in, const int* in_sizes, int n_in,
                              void* d_out, int out_size)
{
    const float* x_in   = (const float*)d_in[0];
    const int*   ei     = (const int*)  d_in[1];
    const float* gender = (const float*)d_in[2];
    const float* handed = (const float*)d_in[3];
    const float* Wih[3] = {(const float*)d_in[4],  (const float*)d_in[8],  (const float*)d_in[12]};
    const float* Whh[3] = {(const float*)d_in[5],  (const float*)d_in[9],  (const float*)d_in[13]};
    const float* bih[3] = {(const float*)d_in[6],  (const float*)d_in[10], (const float*)d_in[14]};
    const float* bhh[3] = {(const float*)d_in[7],  (const float*)d_in[11], (const float*)d_in[15]};
    const float* gW[4]  = {(const float*)d_in[16], (const float*)d_in[18], (const float*)d_in[20], (const float*)d_in[22]};
    const float* gB[4]  = {(const float*)d_in[17], (const float*)d_in[19], (const float*)d_in[21], (const float*)d_in[23]};

    float *xw, *p0, *p1, *seqA, *seqB, *gh, *agg, *deg, *cs1, *cs2;
    cudaGetSymbolAddress((void**)&xw,   g_xw);
    cudaGetSymbolAddress((void**)&p0,   g_p0);
    cudaGetSymbolAddress((void**)&p1,   g_p1);
    cudaGetSymbolAddress((void**)&seqA, g_seqA);
    cudaGetSymbolAddress((void**)&seqB, g_seqB);
    cudaGetSymbolAddress((void**)&gh,   g_gh);
    cudaGetSymbolAddress((void**)&agg,  g_agg);
    cudaGetSymbolAddress((void**)&deg,  g_deg);
    cudaGetSymbolAddress((void**)&cs1,  g_cs1);
    cudaGetSymbolAddress((void**)&cs2,  g_cs2);
    (void)in_sizes; (void)n_in; (void)out_size;

    dim3 gemmGrid(G4 / 128, TT / 128, 2);   // (20, 8, 2) = 320 CTAs
    const int KH0 = ((LEN0 / 2 + 3) / 4) * 4;   // 4252
    const int KH1 = HH / 2;                     // 320
    const int TOT = TT * G4;

    // ---- LSTM layer 0 ----
    k_gemm_nt_sk<<<gemmGrid, 256>>>(x_in, Wih[0], p0, p1, TT, G4, LEN0, KH0);
    k_combine<<<1280, 256>>>(p0, p1, bih[0], bhh[0], xw, TOT, G4);
    k_zero_ctr<<<4, 256>>>();
    k_lstm_scan<<<SB, 160>>>(xw, Whh[0], seqA);
    // ---- LSTM layer 1 ----
    k_gemm_nt_sk<<<gemmGrid, 256>>>(seqA, Wih[1], p0, p1, TT, G4, HH, KH1);
    k_combine<<<1280, 256>>>(p0, p1, bih[1], bhh[1], xw, TOT, G4);
    k_zero_ctr<<<4, 256>>>();
    k_lstm_scan<<<SB, 160>>>(xw, Whh[1], seqB);
    // ---- LSTM layer 2 ----
    k_gemm_nt_sk<<<gemmGrid, 256>>>(seqB, Wih[2], p0, p1, TT, G4, HH, KH1);
    k_combine<<<1280, 256>>>(p0, p1, bih[2], bhh[2], xw, TOT, G4);
    k_zero_ctr<<<4, 256>>>();
    k_lstm_scan<<<SB, 160>>>(xw, Whh[2], seqA);

    // ---- degrees / symmetric norm ----
    k_zero_f<<<4, 256>>>(deg, NN);
    k_deg_count<<<64, 256>>>(ei);
    k_deg_fin<<<4, 256>>>();

    // ---- 4 GCN layers ----
    int dims[5] = {HH, 320, 180, 90, 50};
    const float* xcur = seqA;
    float* bufs[2] = {seqB, seqA};
    for (int l = 0; l < 4; l++) {
        int In = dims[l], Out = dims[l + 1];
        k_gemm_nn<<<dim3((Out + 63) / 64, NN / 64), 256>>>(xcur, gW[l], gh, Out, In);
        k_zero_f<<<320, 256>>>(agg, NN * Out);
        k_zero_f<<<2, 256>>>(cs1, Out);
        k_zero_f<<<2, 256>>>(cs2, Out);
        // warp per edge: 32 threads x (NE + NN) warps
        k_scatter<<<(32 * (NE + NN) + 255) / 256, 256>>>(ei, gh, Out);
        k_act_stats<<<NN, 128>>>(gB[l], Out);
        k_bn<<<NN, 128>>>(bufs[l & 1], Out);
        xcur = bufs[l & 1];
    }

    // ---- pool + FC head ----
    k_pool_fc<<<1, 256>>>(xcur, gender, handed,
                          (const float*)d_in[24], (const float*)d_in[25],
                          (const float*)d_in[26], (const float*)d_in[27],
                          (const float*)d_in[28], (const float*)d_in[29],
                          (float*)d_out);
}